// round 2
// baseline (speedup 1.0000x reference)
#include <cuda_runtime.h>
#include <stdint.h>
#include <math.h>

// ---------------------------------------------------------------------------
// TripletLossWithCurvature: B=8192, D=512, classes<100
// Requires bit-exact JAX Threefry-2x32 reproduction for pos/neg sampling.
// JAX_PARTITIONABLE=1 -> modern default (jax_threefry_partitionable=True).
// If rel_err ~1e-2, flip to 0 (legacy counter layout) next round.
// ---------------------------------------------------------------------------
#define JAX_PARTITIONABLE 1

#define BB 8192
#define DD 512
#define NCLS 128

// Scratch (static __device__ arrays per harness rules; no allocations)
__device__ float g_S[DD*DD];
__device__ float g_G[DD*DD];
__device__ float g_H[BB*DD];
__device__ float g_q[BB];
__device__ float g_musum[DD];
__device__ int   g_lab[BB];
__device__ int   g_cnt[NCLS];
__device__ int   g_off[NCLS];
__device__ int   g_fill[NCLS];
__device__ int   g_list[BB];
__device__ int   g_pos[BB];
__device__ int   g_neg[BB];
__device__ float g_acc[2];   // [0]=loss sum, [1]=n_valid

// ---------------------------------------------------------------------------
// Threefry-2x32, 20 rounds (matches JAX / Random123)
// ---------------------------------------------------------------------------
__device__ __forceinline__ void tf_block(uint32_t k0, uint32_t k1,
                                         uint32_t &x0, uint32_t &x1) {
  uint32_t ks2 = k0 ^ k1 ^ 0x1BD11BDAu;
  x0 += k0; x1 += k1;
#define TF_ROT(x,r) (((x) << (r)) | ((x) >> (32 - (r))))
#define TF_RND(r) { x0 += x1; x1 = TF_ROT(x1, r); x1 ^= x0; }
  TF_RND(13) TF_RND(15) TF_RND(26) TF_RND(6)
  x0 += k1;  x1 += ks2 + 1u;
  TF_RND(17) TF_RND(29) TF_RND(16) TF_RND(24)
  x0 += ks2; x1 += k0 + 2u;
  TF_RND(13) TF_RND(15) TF_RND(26) TF_RND(6)
  x0 += k0;  x1 += k1 + 3u;
  TF_RND(17) TF_RND(29) TF_RND(16) TF_RND(24)
  x0 += k1;  x1 += ks2 + 4u;
  TF_RND(13) TF_RND(15) TF_RND(26) TF_RND(6)
  x0 += ks2; x1 += k0 + 5u;
#undef TF_RND
#undef TF_ROT
}

// split(jax.random.key(42))[which] -> subkey (which=0: pos, which=1: neg)
__device__ __forceinline__ void derive_key(uint32_t which, uint32_t &k0, uint32_t &k1) {
#if JAX_PARTITIONABLE
  uint32_t x0 = 0u, x1 = which;
  tf_block(0u, 42u, x0, x1);
  k0 = x0; k1 = x1;
#else
  // legacy split: counts iota(4) halved -> blocks (0,2) and (1,3)
  uint32_t a0 = 0u, a1 = 2u; tf_block(0u, 42u, a0, a1);
  uint32_t b0 = 1u, b1 = 3u; tf_block(0u, 42u, b0, b1);
  if (which == 0u) { k0 = a0; k1 = b0; } else { k0 = a1; k1 = b1; }
#endif
}

// 32 random bits for flat index p of a (BB,BB) uniform draw
__device__ __forceinline__ uint32_t draw_bits(uint32_t k0, uint32_t k1, uint32_t p) {
#if JAX_PARTITIONABLE
  uint32_t x0 = 0u, x1 = p;
  tf_block(k0, k1, x0, x1);
  return x0 ^ x1;
#else
  const uint32_t half = (uint32_t)BB * (uint32_t)BB / 2u;
  uint32_t x0, x1;
  if (p < half) { x0 = p; x1 = p + half; tf_block(k0, k1, x0, x1); return x0; }
  else          { x0 = p - half; x1 = p; tf_block(k0, k1, x0, x1); return x1; }
#endif
}

// ---------------------------------------------------------------------------
// Kernels
// ---------------------------------------------------------------------------
__global__ void k_zero() {
  int idx = blockIdx.x * blockDim.x + threadIdx.x;
  int stride = gridDim.x * blockDim.x;
  for (int i = idx; i < DD*DD; i += stride) g_S[i] = 0.f;
  if (idx < DD)   g_musum[idx] = 0.f;
  if (idx < NCLS) g_cnt[idx] = 0;
  if (idx < 2)    g_acc[idx] = 0.f;
}

// Detect int64 vs int32 labels, convert, histogram. One block.
__global__ void k_labels(const void* __restrict__ lraw) {
  __shared__ int s_is64;
  if (threadIdx.x == 0) s_is64 = 1;
  __syncthreads();
  const int* w = (const int*)lraw;
  int any = 0;
  for (int k = threadIdx.x; k < 4096; k += 1024)
    if (w[2*k + 1] != 0) any = 1;           // hi-words all 0 iff int64 (labels<100)
  if (any) s_is64 = 0;
  __syncthreads();
  int is64 = s_is64;
  for (int i = threadIdx.x; i < BB; i += 1024) {
    int lab = is64 ? (int)(((const long long*)lraw)[i]) : w[i];
    if (lab < 0) lab = 0;
    if (lab >= NCLS) lab = NCLS - 1;
    g_lab[i] = lab;
    atomicAdd(&g_cnt[lab], 1);
  }
}

__global__ void k_offsets() {
  if (threadIdx.x == 0 && blockIdx.x == 0) {
    int acc = 0;
    for (int c = 0; c < NCLS; c++) { g_off[c] = acc; g_fill[c] = acc; acc += g_cnt[c]; }
  }
}

__global__ void k_scatter() {
  int i = blockIdx.x * blockDim.x + threadIdx.x;
  if (i < BB) {
    int lab = g_lab[i];
    int p = atomicAdd(&g_fill[lab], 1);
    g_list[p] = i;
  }
}

// Positive sampling: one warp per row, iterate only same-class candidates.
__global__ void k_pos() {
  int w = (blockIdx.x * blockDim.x + threadIdx.x) >> 5;
  int lane = threadIdx.x & 31;
  if (w >= BB) return;
  int i = w;
  int lab = g_lab[i];
  int off = g_off[lab], cnt = g_cnt[lab];
  uint32_t kp0, kp1; derive_key(0u, kp0, kp1);
  uint32_t base = (uint32_t)i * (uint32_t)BB;
  uint32_t bestv = 0u; int bestj = 0; int any = 0;
  for (int c = lane; c < cnt; c += 32) {
    int j = g_list[off + c];
    if (j == i) continue;
    uint32_t v = draw_bits(kp0, kp1, base + (uint32_t)j) >> 9;
    if (!any || v > bestv || (v == bestv && j < bestj)) { any = 1; bestv = v; bestj = j; }
  }
  for (int o = 16; o; o >>= 1) {
    uint32_t ov = __shfl_down_sync(0xffffffffu, bestv, o);
    int      oj = __shfl_down_sync(0xffffffffu, bestj, o);
    int      oa = __shfl_down_sync(0xffffffffu, any,  o);
    if (oa && (!any || ov > bestv || (ov == bestv && oj < bestj))) {
      any = 1; bestv = ov; bestj = oj;
    }
  }
  if (lane == 0) g_pos[i] = bestj;
}

// Negative sampling: one block per row, all 8192 candidates (mask same-class).
__global__ void k_neg() {
  __shared__ unsigned char slab[BB];
  __shared__ uint32_t sv[256];
  __shared__ int sj[256];
  int i = blockIdx.x, t = threadIdx.x;
  for (int j = t; j < BB; j += 256) slab[j] = (unsigned char)g_lab[j];
  __syncthreads();
  unsigned char mylab = slab[i];
  uint32_t kn0, kn1; derive_key(1u, kn0, kn1);
  uint32_t base = (uint32_t)i * (uint32_t)BB;
  uint32_t bestv = 0u; int bestj = -1;
  for (int j = t; j < BB; j += 256) {
    if (slab[j] == mylab) continue;
    uint32_t v = draw_bits(kn0, kn1, base + (uint32_t)j) >> 9;
    if (bestj < 0 || v > bestv || (v == bestv && j < bestj)) { bestv = v; bestj = j; }
  }
  sv[t] = bestv; sj[t] = bestj;
  __syncthreads();
  for (int s = 128; s; s >>= 1) {
    if (t < s) {
      uint32_t ov = sv[t + s]; int oj = sj[t + s];
      if (oj >= 0 && (sj[t] < 0 || ov > sv[t] || (ov == sv[t] && oj < sj[t]))) {
        sv[t] = ov; sj[t] = oj;
      }
    }
    __syncthreads();
  }
  if (t == 0) g_neg[i] = (sj[0] >= 0) ? sj[0] : 0;
}

// Column sums for the mean
__global__ void k_mu(const float* __restrict__ F) {
  int c = threadIdx.x;                 // 512 threads
  int r0 = blockIdx.x * 128;           // 64 blocks * 128 rows
  float s = 0.f;
  for (int r = 0; r < 128; r++) s += F[(size_t)(r0 + r) * DD + c];
  atomicAdd(&g_musum[c], s);
}

// S = F^T F, 64x64 tiles, split-K (z = K chunk of 1024)
__global__ void k_syrk(const float* __restrict__ F) {
  __shared__ float As[16][64];
  __shared__ float Bs[16][64];
  int i0 = blockIdx.x * 64, j0 = blockIdx.y * 64;
  int kb = blockIdx.z * 1024;
  int t = threadIdx.x;
  int tx = t & 15, ty = t >> 4;
  float acc[4][4];
#pragma unroll
  for (int u = 0; u < 4; u++)
#pragma unroll
    for (int v = 0; v < 4; v++) acc[u][v] = 0.f;

  for (int k = kb; k < kb + 1024; k += 16) {
#pragma unroll
    for (int r = 0; r < 4; r++) {
      int e = t + 256 * r, kk = e >> 6, c = e & 63;
      As[kk][c] = F[(size_t)(k + kk) * DD + i0 + c];
      Bs[kk][c] = F[(size_t)(k + kk) * DD + j0 + c];
    }
    __syncthreads();
#pragma unroll
    for (int kk = 0; kk < 16; kk++) {
      float a[4], b[4];
#pragma unroll
      for (int u = 0; u < 4; u++) a[u] = As[kk][ty * 4 + u];
#pragma unroll
      for (int v = 0; v < 4; v++) b[v] = Bs[kk][tx * 4 + v];
#pragma unroll
      for (int u = 0; u < 4; u++)
#pragma unroll
        for (int v = 0; v < 4; v++) acc[u][v] += a[u] * b[v];
    }
    __syncthreads();
  }
#pragma unroll
  for (int u = 0; u < 4; u++)
#pragma unroll
    for (int v = 0; v < 4; v++)
      atomicAdd(&g_S[(size_t)(i0 + ty * 4 + u) * DD + j0 + tx * 4 + v], acc[u][v]);
}

// G = S/B - mu mu^T + I
__global__ void k_makeG() {
  int i = blockIdx.x, j = threadIdx.x;
  const float invB = 1.0f / (float)BB;
  float mui = g_musum[i] * invB;
  float muj = g_musum[j] * invB;
  float v = g_S[(size_t)i * DD + j] * invB - mui * muj + (i == j ? 1.0f : 0.0f);
  g_G[(size_t)i * DD + j] = v;
}

// H = F * G  (8192x512 @ 512x512)
__global__ void k_gemmH(const float* __restrict__ F) {
  __shared__ float As[16][65];  // [kk][mm], padded
  __shared__ float Bs[16][64];  // [kk][nn]
  int m0 = blockIdx.x * 64, n0 = blockIdx.y * 64;
  int t = threadIdx.x, tx = t & 15, ty = t >> 4;
  float acc[4][4];
#pragma unroll
  for (int u = 0; u < 4; u++)
#pragma unroll
    for (int v = 0; v < 4; v++) acc[u][v] = 0.f;

  for (int k = 0; k < DD; k += 16) {
#pragma unroll
    for (int r = 0; r < 4; r++) {
      int e = t + 256 * r;
      int kk = e & 15, mm = e >> 4;
      As[kk][mm] = F[(size_t)(m0 + mm) * DD + k + kk];
    }
#pragma unroll
    for (int r = 0; r < 4; r++) {
      int e = t + 256 * r, kk = e >> 6, c = e & 63;
      Bs[kk][c] = g_G[(size_t)(k + kk) * DD + n0 + c];
    }
    __syncthreads();
#pragma unroll
    for (int kk = 0; kk < 16; kk++) {
      float a[4], b[4];
#pragma unroll
      for (int u = 0; u < 4; u++) a[u] = As[kk][ty * 4 + u];
#pragma unroll
      for (int v = 0; v < 4; v++) b[v] = Bs[kk][tx * 4 + v];
#pragma unroll
      for (int u = 0; u < 4; u++)
#pragma unroll
        for (int v = 0; v < 4; v++) acc[u][v] += a[u] * b[v];
    }
    __syncthreads();
  }
#pragma unroll
  for (int u = 0; u < 4; u++)
#pragma unroll
    for (int v = 0; v < 4; v++)
      g_H[(size_t)(m0 + ty * 4 + u) * DD + n0 + tx * 4 + v] = acc[u][v];
}

// q_i = f_i . h_i (one warp per row)
__global__ void k_q(const float* __restrict__ F) {
  int w = (blockIdx.x * blockDim.x + threadIdx.x) >> 5;
  int lane = threadIdx.x & 31;
  if (w >= BB) return;
  const float* f = F + (size_t)w * DD;
  const float* h = g_H + (size_t)w * DD;
  float s = 0.f;
  for (int c = lane; c < DD; c += 32) s += f[c] * h[c];
  for (int o = 16; o; o >>= 1) s += __shfl_down_sync(0xffffffffu, s, o);
  if (lane == 0) g_q[w] = s;
}

// per-sample loss: d^2(i,j) = q_i + q_j - 2 f_i . h_j
__global__ void k_loss(const float* __restrict__ F) {
  __shared__ float rp[128], rn[128];
  int i = blockIdx.x, t = threadIdx.x;
  int p = g_pos[i], n = g_neg[i];
  float sp = 0.f, sn = 0.f;
  const float* f  = F   + (size_t)i * DD;
  const float* hp = g_H + (size_t)p * DD;
  const float* hn = g_H + (size_t)n * DD;
  for (int c = t; c < DD; c += 128) {
    float fv = f[c];
    sp += fv * hp[c];
    sn += fv * hn[c];
  }
  rp[t] = sp; rn[t] = sn;
  __syncthreads();
  for (int s = 64; s; s >>= 1) {
    if (t < s) { rp[t] += rp[t + s]; rn[t] += rn[t + s]; }
    __syncthreads();
  }
  if (t == 0) {
    int lab = g_lab[i];
    int cnt = g_cnt[lab];
    bool valid = (cnt >= 2) && (cnt < BB);
    if (valid) {
      float dp = sqrtf(g_q[i] + g_q[p] - 2.0f * rp[0] + 1e-8f);
      float dn = sqrtf(g_q[i] + g_q[n] - 2.0f * rn[0] + 1e-8f);
      float per = fmaxf(dp - dn + 1.0f, 0.0f);
      atomicAdd(&g_acc[0], per);
      atomicAdd(&g_acc[1], 1.0f);
    }
  }
}

__global__ void k_final(float* __restrict__ out) {
  out[0] = g_acc[0] / fmaxf(g_acc[1], 1.0f);
}

// ---------------------------------------------------------------------------
extern "C" void kernel_launch(void* const* d_in, const int* in_sizes, int n_in,
                              void* d_out, int out_size) {
  const float* F = (const float*)d_in[0];
  const void*  L = d_in[1];
  float* out = (float*)d_out;

  k_zero<<<256, 256>>>();
  k_labels<<<1, 1024>>>(L);
  k_offsets<<<1, 32>>>();
  k_scatter<<<32, 256>>>();
  k_pos<<<BB / 8, 256>>>();
  k_neg<<<BB, 256>>>();
  k_mu<<<64, 512>>>(F);
  {
    dim3 g(8, 8, 8);
    k_syrk<<<g, 256>>>(F);
  }
  k_makeG<<<512, 512>>>();
  {
    dim3 g(128, 8);
    k_gemmH<<<g, 256>>>(F);
  }
  k_q<<<BB / 8, 256>>>(F);
  k_loss<<<BB, 128>>>(F);
  k_final<<<1, 1>>>(out);
}

// round 5
// speedup vs baseline: 1.2322x; 1.2322x over previous
#include <cuda_runtime.h>
#include <stdint.h>
#include <math.h>

// ---------------------------------------------------------------------------
// TripletLossWithCurvature: B=8192, D=512, classes<100
// Bit-exact JAX Threefry-2x32 (partitionable mode — confirmed R2, rel_err 1e-6).
// R3 changes: triangular SYRK (36/64 blocks) + dual-stream overlap of the
// alu-bound sampling chain with the fma-bound GEMM chain.
// ---------------------------------------------------------------------------
#define BB 8192
#define DD 512
#define NCLS 128

// Scratch (static __device__ arrays per harness rules; no allocations)
__device__ float g_S[DD*DD];
__device__ float g_G[DD*DD];
__device__ float g_H[BB*DD];
__device__ float g_q[BB];
__device__ float g_musum[DD];
__device__ int   g_lab[BB];
__device__ int   g_cnt[NCLS];
__device__ int   g_off[NCLS];
__device__ int   g_fill[NCLS];
__device__ int   g_list[BB];
__device__ int   g_pos[BB];
__device__ int   g_neg[BB];
__device__ float g_acc[2];   // [0]=loss sum, [1]=n_valid

// ---------------------------------------------------------------------------
// Threefry-2x32, 20 rounds (matches JAX / Random123)
// ---------------------------------------------------------------------------
__device__ __forceinline__ void tf_block(uint32_t k0, uint32_t k1,
                                         uint32_t &x0, uint32_t &x1) {
  uint32_t ks2 = k0 ^ k1 ^ 0x1BD11BDAu;
  x0 += k0; x1 += k1;
#define TF_ROT(x,r) (((x) << (r)) | ((x) >> (32 - (r))))
#define TF_RND(r) { x0 += x1; x1 = TF_ROT(x1, r); x1 ^= x0; }
  TF_RND(13) TF_RND(15) TF_RND(26) TF_RND(6)
  x0 += k1;  x1 += ks2 + 1u;
  TF_RND(17) TF_RND(29) TF_RND(16) TF_RND(24)
  x0 += ks2; x1 += k0 + 2u;
  TF_RND(13) TF_RND(15) TF_RND(26) TF_RND(6)
  x0 += k0;  x1 += k1 + 3u;
  TF_RND(17) TF_RND(29) TF_RND(16) TF_RND(24)
  x0 += k1;  x1 += ks2 + 4u;
  TF_RND(13) TF_RND(15) TF_RND(26) TF_RND(6)
  x0 += ks2; x1 += k0 + 5u;
#undef TF_RND
#undef TF_ROT
}

// split(jax.random.key(42))[which] -> subkey (which=0: pos, which=1: neg)
__device__ __forceinline__ void derive_key(uint32_t which, uint32_t &k0, uint32_t &k1) {
  uint32_t x0 = 0u, x1 = which;
  tf_block(0u, 42u, x0, x1);
  k0 = x0; k1 = x1;
}

// 32 random bits for flat index p of a (BB,BB) uniform draw (partitionable)
__device__ __forceinline__ uint32_t draw_bits(uint32_t k0, uint32_t k1, uint32_t p) {
  uint32_t x0 = 0u, x1 = p;
  tf_block(k0, k1, x0, x1);
  return x0 ^ x1;
}

// ---------------------------------------------------------------------------
// Kernels
// ---------------------------------------------------------------------------
__global__ void k_zero() {
  int idx = blockIdx.x * blockDim.x + threadIdx.x;
  int stride = gridDim.x * blockDim.x;
  for (int i = idx; i < DD*DD; i += stride) g_S[i] = 0.f;
  if (idx < DD)   g_musum[idx] = 0.f;
  if (idx < NCLS) g_cnt[idx] = 0;
  if (idx < 2)    g_acc[idx] = 0.f;
}

// Detect int64 vs int32 labels, convert, histogram. One block.
__global__ void k_labels(const void* __restrict__ lraw) {
  __shared__ int s_is64;
  if (threadIdx.x == 0) s_is64 = 1;
  __syncthreads();
  const int* w = (const int*)lraw;
  int any = 0;
  for (int k = threadIdx.x; k < 4096; k += 1024)
    if (w[2*k + 1] != 0) any = 1;           // hi-words all 0 iff int64 (labels<100)
  if (any) s_is64 = 0;
  __syncthreads();
  int is64 = s_is64;
  for (int i = threadIdx.x; i < BB; i += 1024) {
    int lab = is64 ? (int)(((const long long*)lraw)[i]) : w[i];
    if (lab < 0) lab = 0;
    if (lab >= NCLS) lab = NCLS - 1;
    g_lab[i] = lab;
    atomicAdd(&g_cnt[lab], 1);
  }
}

__global__ void k_offsets() {
  if (threadIdx.x == 0 && blockIdx.x == 0) {
    int acc = 0;
    for (int c = 0; c < NCLS; c++) { g_off[c] = acc; g_fill[c] = acc; acc += g_cnt[c]; }
  }
}

__global__ void k_scatter() {
  int i = blockIdx.x * blockDim.x + threadIdx.x;
  if (i < BB) {
    int lab = g_lab[i];
    int p = atomicAdd(&g_fill[lab], 1);
    g_list[p] = i;
  }
}

// Positive sampling: one warp per row, iterate only same-class candidates.
__global__ void k_pos() {
  int w = (blockIdx.x * blockDim.x + threadIdx.x) >> 5;
  int lane = threadIdx.x & 31;
  if (w >= BB) return;
  int i = w;
  int lab = g_lab[i];
  int off = g_off[lab], cnt = g_cnt[lab];
  uint32_t kp0, kp1; derive_key(0u, kp0, kp1);
  uint32_t base = (uint32_t)i * (uint32_t)BB;
  uint32_t bestv = 0u; int bestj = 0; int any = 0;
  for (int c = lane; c < cnt; c += 32) {
    int j = g_list[off + c];
    if (j == i) continue;
    uint32_t v = draw_bits(kp0, kp1, base + (uint32_t)j) >> 9;
    if (!any || v > bestv || (v == bestv && j < bestj)) { any = 1; bestv = v; bestj = j; }
  }
  for (int o = 16; o; o >>= 1) {
    uint32_t ov = __shfl_down_sync(0xffffffffu, bestv, o);
    int      oj = __shfl_down_sync(0xffffffffu, bestj, o);
    int      oa = __shfl_down_sync(0xffffffffu, any,  o);
    if (oa && (!any || ov > bestv || (ov == bestv && oj < bestj))) {
      any = 1; bestv = ov; bestj = oj;
    }
  }
  if (lane == 0) g_pos[i] = bestj;
}

// Negative sampling: one block per row, all 8192 candidates (mask same-class).
__global__ void k_neg() {
  __shared__ unsigned char slab[BB];
  __shared__ uint32_t sv[256];
  __shared__ int sj[256];
  int i = blockIdx.x, t = threadIdx.x;
  for (int j = t; j < BB; j += 256) slab[j] = (unsigned char)g_lab[j];
  __syncthreads();
  unsigned char mylab = slab[i];
  uint32_t kn0, kn1; derive_key(1u, kn0, kn1);
  uint32_t base = (uint32_t)i * (uint32_t)BB;
  uint32_t bestv = 0u; int bestj = -1;
  for (int j = t; j < BB; j += 256) {
    if (slab[j] == mylab) continue;
    uint32_t v = draw_bits(kn0, kn1, base + (uint32_t)j) >> 9;
    if (bestj < 0 || v > bestv || (v == bestv && j < bestj)) { bestv = v; bestj = j; }
  }
  sv[t] = bestv; sj[t] = bestj;
  __syncthreads();
  for (int s = 128; s; s >>= 1) {
    if (t < s) {
      uint32_t ov = sv[t + s]; int oj = sj[t + s];
      if (oj >= 0 && (sj[t] < 0 || ov > sv[t] || (ov == sv[t] && oj < sj[t]))) {
        sv[t] = ov; sj[t] = oj;
      }
    }
    __syncthreads();
  }
  if (t == 0) g_neg[i] = (sj[0] >= 0) ? sj[0] : 0;
}

// Column sums for the mean
__global__ void k_mu(const float* __restrict__ F) {
  int c = threadIdx.x;                 // 512 threads
  int r0 = blockIdx.x * 128;           // 64 blocks * 128 rows
  float s = 0.f;
  for (int r = 0; r < 128; r++) s += F[(size_t)(r0 + r) * DD + c];
  atomicAdd(&g_musum[c], s);
}

// S = F^T F, upper-triangle 64x64 block tiles only (36 of 64), split-K (z=8).
__global__ void k_syrk(const float* __restrict__ F) {
  __shared__ float As[16][64];
  __shared__ float Bs[16][64];
  // map blockIdx.x in [0,36) -> (bi,bj), bi<=bj<8
  int rem = blockIdx.x, bi = 0;
  while (rem >= 8 - bi) { rem -= 8 - bi; bi++; }
  int bj = bi + rem;
  int i0 = bi * 64, j0 = bj * 64;
  int kb = blockIdx.z * 1024;
  int t = threadIdx.x;
  int tx = t & 15, ty = t >> 4;
  float acc[4][4];
#pragma unroll
  for (int u = 0; u < 4; u++)
#pragma unroll
    for (int v = 0; v < 4; v++) acc[u][v] = 0.f;

  for (int k = kb; k < kb + 1024; k += 16) {
#pragma unroll
    for (int r = 0; r < 4; r++) {
      int e = t + 256 * r, kk = e >> 6, c = e & 63;
      As[kk][c] = F[(size_t)(k + kk) * DD + i0 + c];
      Bs[kk][c] = F[(size_t)(k + kk) * DD + j0 + c];
    }
    __syncthreads();
#pragma unroll
    for (int kk = 0; kk < 16; kk++) {
      float a[4], b[4];
#pragma unroll
      for (int u = 0; u < 4; u++) a[u] = As[kk][ty * 4 + u];
#pragma unroll
      for (int v = 0; v < 4; v++) b[v] = Bs[kk][tx * 4 + v];
#pragma unroll
      for (int u = 0; u < 4; u++)
#pragma unroll
        for (int v = 0; v < 4; v++) acc[u][v] += a[u] * b[v];
    }
    __syncthreads();
  }
#pragma unroll
  for (int u = 0; u < 4; u++)
#pragma unroll
    for (int v = 0; v < 4; v++)
      atomicAdd(&g_S[(size_t)(i0 + ty * 4 + u) * DD + j0 + tx * 4 + v], acc[u][v]);
}

// G = S/B - mu mu^T + I   (S stored upper-block-triangular: read (min,max))
__global__ void k_makeG() {
  int i = blockIdx.x, j = threadIdx.x;
  const float invB = 1.0f / (float)BB;
  float mui = g_musum[i] * invB;
  float muj = g_musum[j] * invB;
  float s = (i <= j) ? g_S[(size_t)i * DD + j] : g_S[(size_t)j * DD + i];
  float v = s * invB - mui * muj + (i == j ? 1.0f : 0.0f);
  g_G[(size_t)i * DD + j] = v;
}

// H = F * G  (8192x512 @ 512x512)
__global__ void k_gemmH(const float* __restrict__ F) {
  __shared__ float As[16][65];  // [kk][mm], padded
  __shared__ float Bs[16][64];  // [kk][nn]
  int m0 = blockIdx.x * 64, n0 = blockIdx.y * 64;
  int t = threadIdx.x, tx = t & 15, ty = t >> 4;
  float acc[4][4];
#pragma unroll
  for (int u = 0; u < 4; u++)
#pragma unroll
    for (int v = 0; v < 4; v++) acc[u][v] = 0.f;

  for (int k = 0; k < DD; k += 16) {
#pragma unroll
    for (int r = 0; r < 4; r++) {
      int e = t + 256 * r;
      int kk = e & 15, mm = e >> 4;
      As[kk][mm] = F[(size_t)(m0 + mm) * DD + k + kk];
    }
#pragma unroll
    for (int r = 0; r < 4; r++) {
      int e = t + 256 * r, kk = e >> 6, c = e & 63;
      Bs[kk][c] = g_G[(size_t)(k + kk) * DD + n0 + c];
    }
    __syncthreads();
#pragma unroll
    for (int kk = 0; kk < 16; kk++) {
      float a[4], b[4];
#pragma unroll
      for (int u = 0; u < 4; u++) a[u] = As[kk][ty * 4 + u];
#pragma unroll
      for (int v = 0; v < 4; v++) b[v] = Bs[kk][tx * 4 + v];
#pragma unroll
      for (int u = 0; u < 4; u++)
#pragma unroll
        for (int v = 0; v < 4; v++) acc[u][v] += a[u] * b[v];
    }
    __syncthreads();
  }
#pragma unroll
  for (int u = 0; u < 4; u++)
#pragma unroll
    for (int v = 0; v < 4; v++)
      g_H[(size_t)(m0 + ty * 4 + u) * DD + n0 + tx * 4 + v] = acc[u][v];
}

// q_i = f_i . h_i (one warp per row)
__global__ void k_q(const float* __restrict__ F) {
  int w = (blockIdx.x * blockDim.x + threadIdx.x) >> 5;
  int lane = threadIdx.x & 31;
  if (w >= BB) return;
  const float* f = F + (size_t)w * DD;
  const float* h = g_H + (size_t)w * DD;
  float s = 0.f;
  for (int c = lane; c < DD; c += 32) s += f[c] * h[c];
  for (int o = 16; o; o >>= 1) s += __shfl_down_sync(0xffffffffu, s, o);
  if (lane == 0) g_q[w] = s;
}

// per-sample loss: d^2(i,j) = q_i + q_j - 2 f_i . h_j
__global__ void k_loss(const float* __restrict__ F) {
  __shared__ float rp[128], rn[128];
  int i = blockIdx.x, t = threadIdx.x;
  int p = g_pos[i], n = g_neg[i];
  float sp = 0.f, sn = 0.f;
  const float* f  = F   + (size_t)i * DD;
  const float* hp = g_H + (size_t)p * DD;
  const float* hn = g_H + (size_t)n * DD;
  for (int c = t; c < DD; c += 128) {
    float fv = f[c];
    sp += fv * hp[c];
    sn += fv * hn[c];
  }
  rp[t] = sp; rn[t] = sn;
  __syncthreads();
  for (int s = 64; s; s >>= 1) {
    if (t < s) { rp[t] += rp[t + s]; rn[t] += rn[t + s]; }
    __syncthreads();
  }
  if (t == 0) {
    int lab = g_lab[i];
    int cnt = g_cnt[lab];
    bool valid = (cnt >= 2) && (cnt < BB);
    if (valid) {
      float dp = sqrtf(g_q[i] + g_q[p] - 2.0f * rp[0] + 1e-8f);
      float dn = sqrtf(g_q[i] + g_q[n] - 2.0f * rn[0] + 1e-8f);
      float per = fmaxf(dp - dn + 1.0f, 0.0f);
      atomicAdd(&g_acc[0], per);
      atomicAdd(&g_acc[1], 1.0f);
    }
  }
}

__global__ void k_final(float* __restrict__ out) {
  out[0] = g_acc[0] / fmaxf(g_acc[1], 1.0f);
}

// ---------------------------------------------------------------------------
extern "C" void kernel_launch(void* const* d_in, const int* in_sizes, int n_in,
                              void* d_out, int out_size) {
  const float* F = (const float*)d_in[0];
  const void*  L = d_in[1];
  float* out = (float*)d_out;

  // Side stream + fork/join events for overlapping the alu-bound sampling
  // chain with the fma-bound metric chain. Created on first (uncaptured)
  // correctness call; identical launch pattern every call thereafter.
  static cudaStream_t s_samp = nullptr;
  static cudaEvent_t  ev_fork = nullptr, ev_join = nullptr;
  if (s_samp == nullptr) {
    cudaStreamCreateWithFlags(&s_samp, cudaStreamNonBlocking);
    cudaEventCreateWithFlags(&ev_fork, cudaEventDisableTiming);
    cudaEventCreateWithFlags(&ev_join, cudaEventDisableTiming);
  }

  k_zero<<<256, 256>>>();

  // fork: sampling chain on s_samp
  cudaEventRecord(ev_fork, 0);
  cudaStreamWaitEvent(s_samp, ev_fork, 0);
  k_labels<<<1, 1024, 0, s_samp>>>(L);
  k_offsets<<<1, 32, 0, s_samp>>>();
  k_scatter<<<32, 256, 0, s_samp>>>();
  k_pos<<<BB / 8, 256, 0, s_samp>>>();
  k_neg<<<BB, 256, 0, s_samp>>>();
  cudaEventRecord(ev_join, s_samp);

  // metric chain on the main stream (overlaps with sampling)
  k_mu<<<64, 512>>>(F);
  {
    dim3 g(36, 1, 8);
    k_syrk<<<g, 256>>>(F);
  }
  k_makeG<<<512, 512>>>();
  {
    dim3 g(128, 8);
    k_gemmH<<<g, 256>>>(F);
  }
  k_q<<<BB / 8, 256>>>(F);

  // join, then loss
  cudaStreamWaitEvent(0, ev_join, 0);
  k_loss<<<BB, 128>>>(F);
  k_final<<<1, 1>>>(out);
}

// round 7
// speedup vs baseline: 1.2893x; 1.0463x over previous
#include <cuda_runtime.h>
#include <stdint.h>
#include <math.h>

// ---------------------------------------------------------------------------
// TripletLossWithCurvature: B=8192, D=512, classes<100
// Bit-exact JAX Threefry-2x32 (partitionable mode — confirmed, rel_err 1e-6).
// R6: packed fp32 FFMA2 (fma.rn.f32x2) GEMM inner loops (exact arithmetic,
// half the fma-pipe issue), earlier sampling fork, uchar label cache.
// ---------------------------------------------------------------------------
#define BB 8192
#define DD 512
#define NCLS 128

__device__ float g_S[DD*DD];
__device__ float g_G[DD*DD];
__device__ float g_H[BB*DD];
__device__ float g_q[BB];
__device__ float g_musum[DD];
__device__ int   g_lab[BB];
__device__ unsigned char g_lab8[BB];
__device__ int   g_cnt[NCLS];
__device__ int   g_off[NCLS];
__device__ int   g_fill[NCLS];
__device__ int   g_list[BB];
__device__ int   g_pos[BB];
__device__ int   g_neg[BB];
__device__ float g_acc[2];   // [0]=loss sum, [1]=n_valid

// ---------------------------------------------------------------------------
// Packed fp32 helpers (sm_103a f32x2 pipe; IEEE-identical per lane)
// ---------------------------------------------------------------------------
__device__ __forceinline__ void ffma2(unsigned long long &acc,
                                      unsigned long long a2,
                                      unsigned long long b2) {
  asm("fma.rn.f32x2 %0, %1, %2, %0;" : "+l"(acc) : "l"(a2), "l"(b2));
}
__device__ __forceinline__ unsigned long long pack2(float x) {
  unsigned long long r;
  unsigned int xi = __float_as_uint(x);
  asm("mov.b64 %0, {%1, %1};" : "=l"(r) : "r"(xi));
  return r;
}
union U64F2 { unsigned long long u; float2 f; };

// ---------------------------------------------------------------------------
// Threefry-2x32, 20 rounds (matches JAX / Random123)
// ---------------------------------------------------------------------------
__device__ __forceinline__ void tf_block(uint32_t k0, uint32_t k1,
                                         uint32_t &x0, uint32_t &x1) {
  uint32_t ks2 = k0 ^ k1 ^ 0x1BD11BDAu;
  x0 += k0; x1 += k1;
#define TF_ROT(x,r) (((x) << (r)) | ((x) >> (32 - (r))))
#define TF_RND(r) { x0 += x1; x1 = TF_ROT(x1, r); x1 ^= x0; }
  TF_RND(13) TF_RND(15) TF_RND(26) TF_RND(6)
  x0 += k1;  x1 += ks2 + 1u;
  TF_RND(17) TF_RND(29) TF_RND(16) TF_RND(24)
  x0 += ks2; x1 += k0 + 2u;
  TF_RND(13) TF_RND(15) TF_RND(26) TF_RND(6)
  x0 += k0;  x1 += k1 + 3u;
  TF_RND(17) TF_RND(29) TF_RND(16) TF_RND(24)
  x0 += k1;  x1 += ks2 + 4u;
  TF_RND(13) TF_RND(15) TF_RND(26) TF_RND(6)
  x0 += ks2; x1 += k0 + 5u;
#undef TF_RND
#undef TF_ROT
}

__device__ __forceinline__ void derive_key(uint32_t which, uint32_t &k0, uint32_t &k1) {
  uint32_t x0 = 0u, x1 = which;
  tf_block(0u, 42u, x0, x1);
  k0 = x0; k1 = x1;
}

__device__ __forceinline__ uint32_t draw_bits(uint32_t k0, uint32_t k1, uint32_t p) {
  uint32_t x0 = 0u, x1 = p;
  tf_block(k0, k1, x0, x1);
  return x0 ^ x1;
}

// ---------------------------------------------------------------------------
// Kernels
// ---------------------------------------------------------------------------
__global__ void k_zero() {
  int idx = blockIdx.x * blockDim.x + threadIdx.x;
  int stride = gridDim.x * blockDim.x;
  for (int i = idx; i < DD*DD; i += stride) g_S[i] = 0.f;
  if (idx < DD) g_musum[idx] = 0.f;
}

// Zeroes its own counters, detects int64 vs int32, histograms. One block.
__global__ void k_labels(const void* __restrict__ lraw) {
  __shared__ int s_is64;
  if (threadIdx.x < NCLS) g_cnt[threadIdx.x] = 0;
  if (threadIdx.x < 2)    g_acc[threadIdx.x] = 0.f;
  if (threadIdx.x == 0)   s_is64 = 1;
  __syncthreads();
  const int* w = (const int*)lraw;
  int any = 0;
  for (int k = threadIdx.x; k < 4096; k += 1024)
    if (w[2*k + 1] != 0) any = 1;           // hi-words all 0 iff int64 (labels<100)
  if (any) s_is64 = 0;
  __syncthreads();
  int is64 = s_is64;
  for (int i = threadIdx.x; i < BB; i += 1024) {
    int lab = is64 ? (int)(((const long long*)lraw)[i]) : w[i];
    if (lab < 0) lab = 0;
    if (lab >= NCLS) lab = NCLS - 1;
    g_lab[i]  = lab;
    g_lab8[i] = (unsigned char)lab;
    atomicAdd(&g_cnt[lab], 1);
  }
}

__global__ void k_offsets() {
  if (threadIdx.x == 0 && blockIdx.x == 0) {
    int acc = 0;
    for (int c = 0; c < NCLS; c++) { g_off[c] = acc; g_fill[c] = acc; acc += g_cnt[c]; }
  }
}

__global__ void k_scatter() {
  int i = blockIdx.x * blockDim.x + threadIdx.x;
  if (i < BB) {
    int lab = g_lab[i];
    int p = atomicAdd(&g_fill[lab], 1);
    g_list[p] = i;
  }
}

// Positive sampling: one warp per row, same-class candidates only.
__global__ void k_pos() {
  int w = (blockIdx.x * blockDim.x + threadIdx.x) >> 5;
  int lane = threadIdx.x & 31;
  if (w >= BB) return;
  int i = w;
  int lab = g_lab[i];
  int off = g_off[lab], cnt = g_cnt[lab];
  uint32_t kp0, kp1; derive_key(0u, kp0, kp1);
  uint32_t base = (uint32_t)i * (uint32_t)BB;
  uint32_t bestv = 0u; int bestj = 0; int any = 0;
  for (int c = lane; c < cnt; c += 32) {
    int j = g_list[off + c];
    if (j == i) continue;
    uint32_t v = draw_bits(kp0, kp1, base + (uint32_t)j) >> 9;
    if (!any || v > bestv || (v == bestv && j < bestj)) { any = 1; bestv = v; bestj = j; }
  }
  for (int o = 16; o; o >>= 1) {
    uint32_t ov = __shfl_down_sync(0xffffffffu, bestv, o);
    int      oj = __shfl_down_sync(0xffffffffu, bestj, o);
    int      oa = __shfl_down_sync(0xffffffffu, any,  o);
    if (oa && (!any || ov > bestv || (ov == bestv && oj < bestj))) {
      any = 1; bestv = ov; bestj = oj;
    }
  }
  if (lane == 0) g_pos[i] = bestj;
}

// Negative sampling: one block per row, all 8192 candidates.
__global__ void k_neg() {
  __shared__ unsigned char slab[BB];
  __shared__ uint32_t sv[256];
  __shared__ int sj[256];
  int i = blockIdx.x, t = threadIdx.x;
  {
    const uint32_t* l4 = (const uint32_t*)g_lab8;
    uint32_t* s4 = (uint32_t*)slab;
    for (int j = t; j < BB / 4; j += 256) s4[j] = l4[j];
  }
  __syncthreads();
  unsigned char mylab = slab[i];
  uint32_t kn0, kn1; derive_key(1u, kn0, kn1);
  uint32_t base = (uint32_t)i * (uint32_t)BB;
  uint32_t bestv = 0u; int bestj = -1;
  for (int j = t; j < BB; j += 256) {
    if (slab[j] == mylab) continue;
    uint32_t v = draw_bits(kn0, kn1, base + (uint32_t)j) >> 9;
    if (bestj < 0 || v > bestv || (v == bestv && j < bestj)) { bestv = v; bestj = j; }
  }
  sv[t] = bestv; sj[t] = bestj;
  __syncthreads();
  for (int s = 128; s; s >>= 1) {
    if (t < s) {
      uint32_t ov = sv[t + s]; int oj = sj[t + s];
      if (oj >= 0 && (sj[t] < 0 || ov > sv[t] || (ov == sv[t] && oj < sj[t]))) {
        sv[t] = ov; sj[t] = oj;
      }
    }
    __syncthreads();
  }
  if (t == 0) g_neg[i] = (sj[0] >= 0) ? sj[0] : 0;
}

// Column sums for the mean
__global__ void k_mu(const float* __restrict__ F) {
  int c = threadIdx.x;
  int r0 = blockIdx.x * 128;
  float s = 0.f;
  for (int r = 0; r < 128; r++) s += F[(size_t)(r0 + r) * DD + c];
  atomicAdd(&g_musum[c], s);
}

// S = F^T F, upper-triangle 64x64 block tiles (36 of 64), split-K (z=8).
// Inner loop uses packed FFMA2.
__global__ void k_syrk(const float* __restrict__ F) {
  __shared__ float As[16][64];
  __shared__ float Bs[16][64];
  int rem = blockIdx.x, bi = 0;
  while (rem >= 8 - bi) { rem -= 8 - bi; bi++; }
  int bj = bi + rem;
  int i0 = bi * 64, j0 = bj * 64;
  int kb = blockIdx.z * 1024;
  int t = threadIdx.x;
  int tx = t & 15, ty = t >> 4;
  unsigned long long acc2[4][2];
#pragma unroll
  for (int u = 0; u < 4; u++) { acc2[u][0] = 0ull; acc2[u][1] = 0ull; }

  for (int k = kb; k < kb + 1024; k += 16) {
#pragma unroll
    for (int r = 0; r < 4; r++) {
      int e = t + 256 * r, kk = e >> 6, c = e & 63;
      As[kk][c] = F[(size_t)(k + kk) * DD + i0 + c];
      Bs[kk][c] = F[(size_t)(k + kk) * DD + j0 + c];
    }
    __syncthreads();
#pragma unroll
    for (int kk = 0; kk < 16; kk++) {
      unsigned long long aa[4], bb[2];
      const unsigned long long* bp =
          (const unsigned long long*)&Bs[kk][tx * 4];
      bb[0] = bp[0]; bb[1] = bp[1];
#pragma unroll
      for (int u = 0; u < 4; u++) aa[u] = pack2(As[kk][ty * 4 + u]);
#pragma unroll
      for (int u = 0; u < 4; u++) {
        ffma2(acc2[u][0], aa[u], bb[0]);
        ffma2(acc2[u][1], aa[u], bb[1]);
      }
    }
    __syncthreads();
  }
#pragma unroll
  for (int u = 0; u < 4; u++) {
#pragma unroll
    for (int v2 = 0; v2 < 2; v2++) {
      U64F2 cv; cv.u = acc2[u][v2];
      size_t row = (size_t)(i0 + ty * 4 + u) * DD + j0 + tx * 4 + v2 * 2;
      atomicAdd(&g_S[row],     cv.f.x);
      atomicAdd(&g_S[row + 1], cv.f.y);
    }
  }
}

// G = S/B - mu mu^T + I   (S stored upper-block-triangular: read (min,max))
__global__ void k_makeG() {
  int i = blockIdx.x, j = threadIdx.x;
  const float invB = 1.0f / (float)BB;
  float mui = g_musum[i] * invB;
  float muj = g_musum[j] * invB;
  float s = (i <= j) ? g_S[(size_t)i * DD + j] : g_S[(size_t)j * DD + i];
  float v = s * invB - mui * muj + (i == j ? 1.0f : 0.0f);
  g_G[(size_t)i * DD + j] = v;
}

// H = F * G  (8192x512 @ 512x512), packed FFMA2 inner loop.
__global__ void k_gemmH(const float* __restrict__ F) {
  __shared__ float As[16][65];  // [kk][mm], padded
  __shared__ float Bs[16][64];  // [kk][nn]
  int m0 = blockIdx.x * 64, n0 = blockIdx.y * 64;
  int t = threadIdx.x, tx = t & 15, ty = t >> 4;
  unsigned long long acc2[4][2];
#pragma unroll
  for (int u = 0; u < 4; u++) { acc2[u][0] = 0ull; acc2[u][1] = 0ull; }

  for (int k = 0; k < DD; k += 16) {
#pragma unroll
    for (int r = 0; r < 4; r++) {
      int e = t + 256 * r;
      int kk = e & 15, mm = e >> 4;
      As[kk][mm] = F[(size_t)(m0 + mm) * DD + k + kk];
    }
#pragma unroll
    for (int r = 0; r < 4; r++) {
      int e = t + 256 * r, kk = e >> 6, c = e & 63;
      Bs[kk][c] = g_G[(size_t)(k + kk) * DD + n0 + c];
    }
    __syncthreads();
#pragma unroll
    for (int kk = 0; kk < 16; kk++) {
      unsigned long long aa[4], bb[2];
      const unsigned long long* bp =
          (const unsigned long long*)&Bs[kk][tx * 4];
      bb[0] = bp[0]; bb[1] = bp[1];
#pragma unroll
      for (int u = 0; u < 4; u++) aa[u] = pack2(As[kk][ty * 4 + u]);
#pragma unroll
      for (int u = 0; u < 4; u++) {
        ffma2(acc2[u][0], aa[u], bb[0]);
        ffma2(acc2[u][1], aa[u], bb[1]);
      }
    }
    __syncthreads();
  }
#pragma unroll
  for (int u = 0; u < 4; u++) {
    U64F2 lo, hi; lo.u = acc2[u][0]; hi.u = acc2[u][1];
    float4 o; o.x = lo.f.x; o.y = lo.f.y; o.z = hi.f.x; o.w = hi.f.y;
    *(float4*)&g_H[(size_t)(m0 + ty * 4 + u) * DD + n0 + tx * 4] = o;
  }
}

// q_i = f_i . h_i (one warp per row)
__global__ void k_q(const float* __restrict__ F) {
  int w = (blockIdx.x * blockDim.x + threadIdx.x) >> 5;
  int lane = threadIdx.x & 31;
  if (w >= BB) return;
  const float* f = F + (size_t)w * DD;
  const float* h = g_H + (size_t)w * DD;
  float s = 0.f;
  for (int c = lane; c < DD; c += 32) s += f[c] * h[c];
  for (int o = 16; o; o >>= 1) s += __shfl_down_sync(0xffffffffu, s, o);
  if (lane == 0) g_q[w] = s;
}

// per-sample loss: d^2(i,j) = q_i + q_j - 2 f_i . h_j
__global__ void k_loss(const float* __restrict__ F) {
  __shared__ float rp[128], rn[128];
  int i = blockIdx.x, t = threadIdx.x;
  int p = g_pos[i], n = g_neg[i];
  float sp = 0.f, sn = 0.f;
  const float* f  = F   + (size_t)i * DD;
  const float* hp = g_H + (size_t)p * DD;
  const float* hn = g_H + (size_t)n * DD;
  for (int c = t; c < DD; c += 128) {
    float fv = f[c];
    sp += fv * hp[c];
    sn += fv * hn[c];
  }
  rp[t] = sp; rn[t] = sn;
  __syncthreads();
  for (int s = 64; s; s >>= 1) {
    if (t < s) { rp[t] += rp[t + s]; rn[t] += rn[t + s]; }
    __syncthreads();
  }
  if (t == 0) {
    int lab = g_lab[i];
    int cnt = g_cnt[lab];
    bool valid = (cnt >= 2) && (cnt < BB);
    if (valid) {
      float dp = sqrtf(g_q[i] + g_q[p] - 2.0f * rp[0] + 1e-8f);
      float dn = sqrtf(g_q[i] + g_q[n] - 2.0f * rn[0] + 1e-8f);
      float per = fmaxf(dp - dn + 1.0f, 0.0f);
      atomicAdd(&g_acc[0], per);
      atomicAdd(&g_acc[1], 1.0f);
    }
  }
}

__global__ void k_final(float* __restrict__ out) {
  out[0] = g_acc[0] / fmaxf(g_acc[1], 1.0f);
}

// ---------------------------------------------------------------------------
extern "C" void kernel_launch(void* const* d_in, const int* in_sizes, int n_in,
                              void* d_out, int out_size) {
  const float* F = (const float*)d_in[0];
  const void*  L = d_in[1];
  float* out = (float*)d_out;

  static cudaStream_t s_samp = nullptr;
  static cudaEvent_t  ev_fork = nullptr, ev_join = nullptr;
  if (s_samp == nullptr) {
    cudaStreamCreateWithFlags(&s_samp, cudaStreamNonBlocking);
    cudaEventCreateWithFlags(&ev_fork, cudaEventDisableTiming);
    cudaEventCreateWithFlags(&ev_join, cudaEventDisableTiming);
  }

  // fork immediately: sampling chain is independent of the metric chain
  cudaEventRecord(ev_fork, 0);
  cudaStreamWaitEvent(s_samp, ev_fork, 0);
  k_labels<<<1, 1024, 0, s_samp>>>(L);
  k_offsets<<<1, 32, 0, s_samp>>>();
  k_scatter<<<32, 256, 0, s_samp>>>();
  k_pos<<<BB / 8, 256, 0, s_samp>>>();
  k_neg<<<BB, 256, 0, s_samp>>>();
  cudaEventRecord(ev_join, s_samp);

  // metric chain on the main stream
  k_zero<<<256, 256>>>();
  k_mu<<<64, 512>>>(F);
  {
    dim3 g(36, 1, 8);
    k_syrk<<<g, 256>>>(F);
  }
  k_makeG<<<512, 512>>>();
  {
    dim3 g(128, 8);
    k_gemmH<<<g, 256>>>(F);
  }
  k_q<<<BB / 8, 256>>>(F);

  cudaStreamWaitEvent(0, ev_join, 0);
  k_loss<<<BB, 128>>>(F);
  k_final<<<1, 1>>>(out);
}